// round 12
// baseline (speedup 1.0000x reference)
#include <cuda_runtime.h>
#include <math.h>

// Problem constants
#define NN    65536
#define EE    1048576
#define TPAST 20
#define TFUT  40
#define HK    48
#define H3    144
#define D3    432

#define CAP1  4096
#define CAPE  16384
#define MAX2  8192

#define NB    1024    // edge-pass grid
#define GGRU  148     // gru grid: 148 blocks x 2 sub-blocks = 296 slots (one wave)

#define SUBSYNC(id) asm volatile("bar.sync %0, 160;" :: "r"(id) : "memory")

// ---------------- device scratch ----------------
__device__ float g_deg[NN];
__device__ int   g_slot1[NN];
__device__ int   g_slot2[NN];
__device__ unsigned g_bm1[NN / 32];
__device__ unsigned g_bm12[NN / 32];
__device__ int   g_s1rows[CAP1];
__device__ float g_s1w[CAP1];
__device__ int   g_s1nodes[CAP1];
__device__ int   g_s2erow[CAPE];
__device__ int   g_s2ecol[CAPE];
__device__ float g_s2ew[CAPE];
__device__ int   g_s2nodes[MAX2];
__device__ float g_xw1[MAX2 * HK];
__device__ float g_x1[CAP1 * HK];
__device__ float g_x1acc[CAP1 * HK];
__device__ float g_interact[HK];
__device__ float g_target[HK];
__device__ float g_futv[HK];
__device__ int g_s1cnt = 0, g_n1 = 0, g_s2ecnt = 0, g_n2 = 0;
__device__ int g_doneA = 0;

__device__ __forceinline__ float sigmoidf(float x) { return 1.0f / (1.0f + __expf(-x)); }
__device__ __forceinline__ float sigmoidp(float x) { return 1.0f / (1.0f + expf(-x)); }

// ---------------- passA: striped init + scan in-edges of node 0; last block builds S1 ----------------
__global__ void k_passA(const int* __restrict__ ei, const float* __restrict__ ew) {
    int tid = threadIdx.x;
    int gt = blockIdx.x * 256 + tid;
    if (gt < NN) { g_deg[gt] = 0.f; g_slot1[gt] = -1; g_slot2[gt] = -1; }
    if (gt < NN / 32) { g_bm1[gt] = 0u; g_bm12[gt] = 0u; }
    if (gt < CAP1 * HK) g_x1acc[gt] = 0.f;
    if (gt < EE / 4) {
        int4 c = reinterpret_cast<const int4*>(ei + EE)[gt];
        if (c.x == 0 || c.y == 0 || c.z == 0 || c.w == 0) {
            int cc[4] = {c.x, c.y, c.z, c.w};
            #pragma unroll
            for (int q = 0; q < 4; q++) {
                if (cc[q] == 0) {
                    int e = gt * 4 + q;
                    int pos = atomicAdd(&g_s1cnt, 1);
                    if (pos < CAP1) { g_s1rows[pos] = ei[e]; g_s1w[pos] = ew[e]; }
                }
            }
        }
    }
    __threadfence();
    __syncthreads();
    __shared__ int slast;
    if (tid == 0) slast = (atomicAdd(&g_doneA, 1) == NB - 1) ? 1 : 0;
    __syncthreads();
    if (!slast) return;
    __threadfence();
    int n = min(g_s1cnt, CAP1);
    for (int i = tid; i <= n; i += 256) {
        int v = (i == n) ? 0 : g_s1rows[i];
        if (atomicCAS(&g_slot1[v], -1, -2) == -1) {
            int s = atomicAdd(&g_n1, 1);
            if (s < CAP1) g_s1nodes[s] = v;
            g_slot1[v] = s;
            atomicOr(&g_bm1[v >> 5], 1u << (v & 31));
        }
        if (atomicCAS(&g_slot2[v], -1, -2) == -1) {
            int s = atomicAdd(&g_n2, 1);
            if (s < MAX2) g_s2nodes[s] = v;
            g_slot2[v] = s;
            g_deg[v] = 1.0f;
            atomicOr(&g_bm12[v >> 5], 1u << (v & 31));
        }
    }
    __syncthreads();
    if (tid == 0) g_doneA = 0;
}

// ---------------- passB ----------------
__global__ void k_passB(const int* __restrict__ ei, const float* __restrict__ ew) {
    int e4 = blockIdx.x * 256 + threadIdx.x;
    if (e4 >= EE / 4) return;
    int4 c = reinterpret_cast<const int4*>(ei + EE)[e4];
    int cc[4] = {c.x, c.y, c.z, c.w};
    #pragma unroll
    for (int q = 0; q < 4; q++) {
        int col = cc[q];
        if ((g_bm1[col >> 5] >> (col & 31)) & 1u) {
            int e = e4 * 4 + q;
            int row = ei[e];
            int pos = atomicAdd(&g_s2ecnt, 1);
            if (pos < CAPE) { g_s2erow[pos] = row; g_s2ecol[pos] = col; g_s2ew[pos] = ew[e]; }
            if (atomicCAS(&g_slot2[row], -1, -2) == -1) {
                int s = atomicAdd(&g_n2, 1);
                if (s < MAX2) g_s2nodes[s] = row;
                g_slot2[row] = s;
                g_deg[row] = 1.0f;
                atomicOr(&g_bm12[row >> 5], 1u << (row & 31));
            }
        }
    }
}

// ---------------- passC ----------------
__global__ void k_passC(const int* __restrict__ ei, const float* __restrict__ ew) {
    int e4 = blockIdx.x * 256 + threadIdx.x;
    if (e4 >= EE / 4) return;
    int4 c = reinterpret_cast<const int4*>(ei + EE)[e4];
    int cc[4] = {c.x, c.y, c.z, c.w};
    #pragma unroll
    for (int q = 0; q < 4; q++) {
        int col = cc[q];
        if ((g_bm12[col >> 5] >> (col & 31)) & 1u)
            atomicAdd(&g_deg[col], ew[e4 * 4 + q]);
    }
}

// ---------------- conv1d+GRU sequence (per 160-thread sub-block, named barrier) ----------------
__device__ void gru_seq_sub(const float* __restrict__ xin, int T, bool act,
                            const float* __restrict__ cw, const float* __restrict__ cb,
                            const float* __restrict__ Wih, const float* __restrict__ Whh,
                            const float* __restrict__ bih, const float* __restrict__ bhh,
                            float* xs, float* xe, float* ga, float* gb, float* h,
                            int st, int bar) {
    for (int i = st; i < 2 * T; i += 160) xs[i] = act ? xin[i] : 0.f;
    if (st < HK) h[st] = 0.f;
    SUBSYNC(bar);
    for (int idx = st; idx < T * HK; idx += 160) {
        int t = idx / HK, k = idx - t * HK;
        float acc = cb[k];
        #pragma unroll
        for (int j = 0; j < 3; j++) {
            int tt = t + j - 1;
            if (tt >= 0 && tt < T)
                acc += xs[tt * 2 + 0] * cw[(k * 2 + 0) * 3 + j]
                     + xs[tt * 2 + 1] * cw[(k * 2 + 1) * 3 + j];
        }
        xe[idx] = fmaxf(acc, 0.f);
    }
    float wi[HK], wh[HK];
    float bi = 0.f, bh = 0.f;
    if (st < H3) {
        #pragma unroll
        for (int j = 0; j < HK; j++) { wi[j] = Wih[st * HK + j]; wh[j] = Whh[st * HK + j]; }
        bi = bih[st]; bh = bhh[st];
    }
    SUBSYNC(bar);
    for (int t = 0; t < T; t++) {
        if (st < H3) {
            float a0 = bi, a1 = 0.f, b0 = bh, b1 = 0.f;
            const float* xt = &xe[t * HK];
            #pragma unroll
            for (int j = 0; j < HK; j += 2) {
                a0 += wi[j] * xt[j];     a1 += wi[j + 1] * xt[j + 1];
                b0 += wh[j] * h[j];      b1 += wh[j + 1] * h[j + 1];
            }
            ga[st] = a0 + a1; gb[st] = b0 + b1;
        }
        SUBSYNC(bar);
        float hn = 0.f;
        if (st < HK) {
            float r = sigmoidp(ga[st] + gb[st]);
            float z = sigmoidp(ga[HK + st] + gb[HK + st]);
            float n = tanhf(ga[2 * HK + st] + r * gb[2 * HK + st]);
            hn = (1.f - z) * n + z * h[st];
        }
        SUBSYNC(bar);
        if (st < HK) h[st] = hn;
        SUBSYNC(bar);
    }
}

// two sub-blocks of 160 threads, each runs one GRU sequence; 296 slots = one wave
__global__ __launch_bounds__(320, 1) void k_gru_all(
    const float* __restrict__ x,
    const float* __restrict__ past, const float* __restrict__ future,
    const float* __restrict__ cpw, const float* __restrict__ cpb,
    const float* __restrict__ cfw, const float* __restrict__ cfb,
    const float* __restrict__ pWih, const float* __restrict__ pWhh,
    const float* __restrict__ pbih, const float* __restrict__ pbhh,
    const float* __restrict__ fWih, const float* __restrict__ fWhh,
    const float* __restrict__ fbih, const float* __restrict__ fbhh,
    const float* __restrict__ g1w) {
    __shared__ float xs[2][2 * TFUT], xe[2][TFUT * HK], ga[2][H3], gb[2][H3], h[2][HK];
    int tid = threadIdx.x;
    int sub = tid / 160, st = tid - sub * 160;
    int bar = sub + 1;
    int n2 = min(g_n2, MAX2);
    int count = n2 + 2;
    int slots = GGRU * 2;
    int iters = (count + slots - 1) / slots;   // uniform across all slots
    for (int it = 0; it < iters; it++) {
        int idx = blockIdx.x * 2 + sub + it * slots;
        bool act = idx < count;
        if (idx == 0) {
            gru_seq_sub(past, TPAST, act, cpw, cpb, pWih, pWhh, pbih, pbhh,
                        xs[sub], xe[sub], ga[sub], gb[sub], h[sub], st, bar);
            if (act && st < HK) g_target[st] = h[sub][st];
        } else if (idx == 1) {
            gru_seq_sub(future, TFUT, act, cfw, cfb, fWih, fWhh, fbih, fbhh,
                        xs[sub], xe[sub], ga[sub], gb[sub], h[sub], st, bar);
            if (act && st < HK) g_futv[st] = h[sub][st];
        } else {
            int i = act ? (idx - 2) : 0;
            int node = (i < n2) ? g_s2nodes[i] : 0;
            gru_seq_sub(x + (size_t)node * (2 * TPAST), TPAST, act,
                        cpw, cpb, pWih, pWhh, pbih, pbhh,
                        xs[sub], xe[sub], ga[sub], gb[sub], h[sub], st, bar);
            if (act && st < HK) {
                float acc = 0.f;
                #pragma unroll
                for (int j = 0; j < HK; j++) acc += h[sub][j] * g1w[st * HK + j];
                g_xw1[i * HK + st] = acc;
            }
            SUBSYNC(bar);
        }
    }
}

// ---------------- GCN cone ----------------
__global__ void k_layer1() {
    int ne = min(g_s2ecnt, CAPE);
    int total = ne * HK;
    int stride = gridDim.x * blockDim.x;
    for (int idx = blockIdx.x * blockDim.x + threadIdx.x; idx < total; idx += stride) {
        int e = idx / HK, k = idx - e * HK;
        int row = g_s2erow[e], col = g_s2ecol[e];
        float norm = rsqrtf(g_deg[row]) * g_s2ew[e] * rsqrtf(g_deg[col]);
        int s2 = g_slot2[row];
        int s1 = g_slot1[col];
        if (s2 >= 0 && s2 < MAX2 && s1 >= 0 && s1 < CAP1)
            atomicAdd(&g_x1acc[s1 * HK + k], g_xw1[s2 * HK + k] * norm);
    }
}

__global__ void k_layer2(const float* __restrict__ b1,
                         const float* __restrict__ g2w, const float* __restrict__ g2b) {
    __shared__ float coef[1024];
    __shared__ float xagg[HK];
    int tid = threadIdx.x;
    int n1 = min(g_n1, CAP1);
    for (int idx = tid; idx < n1 * HK; idx += blockDim.x) {
        int s = idx / HK, k = idx - s * HK;
        int v = g_s1nodes[s];
        float self = g_xw1[g_slot2[v] * HK + k] / g_deg[v];
        g_x1[idx] = fmaxf(g_x1acc[idx] + self + b1[k], 0.f);
    }
    int n1c = min(n1, 1024);
    int ncnt = min(g_s1cnt, CAP1);
    for (int i = tid; i < n1c; i += blockDim.x) coef[i] = 0.f;
    __syncthreads();
    float d0 = rsqrtf(g_deg[0]);
    for (int i = tid; i < ncnt; i += blockDim.x) {
        int row = g_s1rows[i];
        float nrm = rsqrtf(g_deg[row]) * g_s1w[i] * d0;
        int s = g_slot1[row];
        if (s >= 0 && s < n1c) atomicAdd(&coef[s], nrm);
    }
    __syncthreads();
    if (tid == 0) coef[g_slot1[0]] += 1.0f / g_deg[0];
    __syncthreads();
    if (tid < HK) {
        float a = 0.f;
        for (int s = 0; s < n1c; s++) a += coef[s] * g_x1[s * HK + tid];
        xagg[tid] = a;
    }
    __syncthreads();
    if (tid < HK) {
        float a = g2b[tid];
        #pragma unroll
        for (int j = 0; j < HK; j++) a += xagg[j] * g2w[tid * HK + j];
        g_interact[tid] = a;
    }
    __syncthreads();
    if (tid == 0) { g_s1cnt = 0; g_n1 = 0; g_s2ecnt = 0; g_n2 = 0; }
}

// ---------------- decoder: h-dim partitioned cluster, st.async + mbarrier (proven) ----------------
__device__ __forceinline__ unsigned smem_u32(const void* p) {
    return (unsigned)__cvta_generic_to_shared(p);
}
__device__ __forceinline__ unsigned ctarank_() {
    unsigned r; asm("mov.u32 %0, %%cluster_ctarank;" : "=r"(r)); return r;
}
__device__ __forceinline__ void mbar_init(unsigned mbar, unsigned cnt) {
    asm volatile("mbarrier.init.shared.b64 [%0], %1;" :: "r"(mbar), "r"(cnt) : "memory");
}
__device__ __forceinline__ void mbar_arrive_expect(unsigned mbar, unsigned bytes) {
    asm volatile("mbarrier.arrive.expect_tx.shared.b64 _, [%0], %1;"
                 :: "r"(mbar), "r"(bytes) : "memory");
}
__device__ __forceinline__ void mbar_wait(unsigned mbar, unsigned phase) {
    asm volatile(
        "{\n\t.reg .pred P;\n\t"
        "WL_%=:\n\t"
        "mbarrier.try_wait.parity.shared.b64 P, [%0], %1;\n\t"
        "@!P bra WL_%=;\n\t}"
        :: "r"(mbar), "r"(phase) : "memory");
}
__device__ __forceinline__ void st_async_f32(unsigned raddr, float v, unsigned rmbar) {
    asm volatile("st.async.shared::cluster.mbarrier::complete_tx::bytes.f32 [%0], %1, [%2];"
                 :: "r"(raddr), "f"(v), "r"(rmbar) : "memory");
}
__device__ __forceinline__ unsigned mapa_(unsigned laddr, unsigned rank) {
    unsigned r;
    asm volatile("mapa.shared::cluster.u32 %0, %1, %2;" : "=r"(r) : "r"(laddr), "r"(rank));
    return r;
}

__global__ __launch_bounds__(432, 1) __cluster_dims__(3, 1, 1)
void k_decoder(const float* __restrict__ past,
               const float* __restrict__ dWih, const float* __restrict__ dWhh,
               const float* __restrict__ dbih, const float* __restrict__ dbhh,
               const float* __restrict__ fcw, const float* __restrict__ fcb,
               float* __restrict__ out) {
    __shared__ __align__(16) float hbuf[2][H3];
    __shared__ float part[432];
    __shared__ float gbl[H3];
    __shared__ float ga0[H3];
    __shared__ float sbihL[H3], sbhhL[H3];
    __shared__ float sc[H3];
    __shared__ float sfcw[2 * H3];
    __shared__ float pres[2];
    __shared__ __align__(8) unsigned long long mbs[2];

    int tid = threadIdx.x;
    unsigned ct = ctarank_();
    int rl = tid % H3, p = tid / H3;
    int grow = (rl / 48) * H3 + (int)ct * 48 + (rl % 48);

    unsigned mb0 = smem_u32(&mbs[0]), mb1 = smem_u32(&mbs[1]);
    if (tid == 0) { mbar_init(mb0, 1); mbar_init(mb1, 1); }

    float w[48];
    {
        const float4* wp = reinterpret_cast<const float4*>(dWhh + grow * H3 + p * 48);
        #pragma unroll
        for (int j = 0; j < 12; j++) {
            float4 v = wp[j];
            w[4 * j + 0] = v.x; w[4 * j + 1] = v.y; w[4 * j + 2] = v.z; w[4 * j + 3] = v.w;
        }
    }
    if (tid < HK) { sc[tid] = g_interact[tid]; sc[HK + tid] = g_target[tid]; sc[2 * HK + tid] = g_futv[tid]; }
    if (tid < H3) { hbuf[0][tid] = 0.f; sbihL[tid] = dbih[grow]; sbhhL[tid] = dbhh[grow]; }
    if (ct == 0) {
        if (tid >= H3 && tid < H3 + 2 * H3) sfcw[tid - H3] = fcw[tid - H3];
        if (tid < 2) pres[tid] = past[(TPAST - 1) * 2 + tid];
    }
    __syncthreads();

    {
        float a = 0.f;
        const float* wi = dWih + grow * H3 + p * 48;
        #pragma unroll
        for (int j = 0; j < 48; j++) a += wi[j] * sc[p * 48 + j];
        part[tid] = a;
    }
    __syncthreads();
    if (tid < H3) ga0[tid] = part[tid] + part[tid + H3] + part[tid + 2 * H3] + sbihL[tid];
    __syncthreads();
    asm volatile("barrier.cluster.arrive.aligned;" ::: "memory");
    asm volatile("barrier.cluster.wait.aligned;" ::: "memory");

    int base = (int)ct * 48;
    for (int i = 0; i < TFUT; i++) {
        int cur = i & 1, bi = cur ^ 1;
        unsigned mbar = bi ? mb1 : mb0;
        unsigned ph = (i >> 1) & 1;
        {
            const float4* hp4 = reinterpret_cast<const float4*>(&hbuf[cur][p * 48]);
            float a0 = 0.f, a1 = 0.f, a2 = 0.f, a3 = 0.f;
            #pragma unroll
            for (int j = 0; j < 12; j++) {
                float4 hv = hp4[j];
                a0 += w[4 * j + 0] * hv.x;
                a1 += w[4 * j + 1] * hv.y;
                a2 += w[4 * j + 2] * hv.z;
                a3 += w[4 * j + 3] * hv.w;
            }
            part[tid] = (a0 + a1) + (a2 + a3);
        }
        __syncthreads();
        if (tid < H3) gbl[tid] = part[tid] + part[tid + H3] + part[tid + 2 * H3] + sbhhL[tid];
        __syncthreads();
        if (tid < 48) {
            float gar = i ? sbihL[tid]      : ga0[tid];
            float gaz = i ? sbihL[48 + tid] : ga0[48 + tid];
            float gan = i ? sbihL[96 + tid] : ga0[96 + tid];
            float r = sigmoidf(gar + gbl[tid]);
            float z = sigmoidf(gaz + gbl[48 + tid]);
            float n = tanhf(gan + r * gbl[96 + tid]);
            float hn = (1.f - z) * n + z * hbuf[cur][base + tid];
            hbuf[bi][base + tid] = hn;
            unsigned la = smem_u32(&hbuf[bi][base + tid]);
            st_async_f32(mapa_(la, (ct + 1) % 3), hn, mapa_(mbar, (ct + 1) % 3));
            st_async_f32(mapa_(la, (ct + 2) % 3), hn, mapa_(mbar, (ct + 2) % 3));
        }
        if (tid == 64) mbar_arrive_expect(mbar, 384);
        __syncthreads();
        mbar_wait(mbar, ph);
        if (ct == 0 && tid >= 64 && tid < 128) {
            int d = (tid - 64) >> 5, lane = tid & 31;
            float a = 0.f;
            #pragma unroll
            for (int j = lane; j < H3; j += 32) a += hbuf[bi][j] * sfcw[d * H3 + j];
            #pragma unroll
            for (int off = 16; off; off >>= 1) a += __shfl_down_sync(0xffffffffu, a, off);
            if (lane == 0) { pres[d] += a + fcb[d]; out[i * 2 + d] = pres[d]; }
        }
        __syncthreads();
    }
}

// ---------------- launch ----------------
extern "C" void kernel_launch(void* const* d_in, const int* in_sizes, int n_in,
                              void* d_out, int out_size) {
    (void)in_sizes; (void)n_in; (void)out_size;
    const float* past   = (const float*)d_in[0];
    const float* future = (const float*)d_in[1];
    const float* x      = (const float*)d_in[2];
    const int*   ei     = (const int*)  d_in[3];
    const float* ew     = (const float*)d_in[4];
    const float* cpw  = (const float*)d_in[5];
    const float* cpb  = (const float*)d_in[6];
    const float* cfw  = (const float*)d_in[7];
    const float* cfb  = (const float*)d_in[8];
    const float* pWih = (const float*)d_in[9];
    const float* pWhh = (const float*)d_in[10];
    const float* pbih = (const float*)d_in[11];
    const float* pbhh = (const float*)d_in[12];
    const float* fWih = (const float*)d_in[13];
    const float* fWhh = (const float*)d_in[14];
    const float* fbih = (const float*)d_in[15];
    const float* fbhh = (const float*)d_in[16];
    const float* dWih = (const float*)d_in[17];
    const float* dWhh = (const float*)d_in[18];
    const float* dbih = (const float*)d_in[19];
    const float* dbhh = (const float*)d_in[20];
    const float* fcw  = (const float*)d_in[21];
    const float* fcb  = (const float*)d_in[22];
    const float* g1w  = (const float*)d_in[23];
    const float* g1b  = (const float*)d_in[24];
    const float* g2w  = (const float*)d_in[25];
    const float* g2b  = (const float*)d_in[26];
    float* out = (float*)d_out;

    k_passA<<<NB, 256>>>(ei, ew);
    k_passB<<<NB, 256>>>(ei, ew);
    k_passC<<<NB, 256>>>(ei, ew);
    k_gru_all<<<GGRU, 320>>>(x, past, future, cpw, cpb, cfw, cfb,
                             pWih, pWhh, pbih, pbhh, fWih, fWhh, fbih, fbhh, g1w);
    k_layer1<<<64, 256>>>();
    k_layer2<<<1, 256>>>(g1b, g2w, g2b);
    k_decoder<<<3, 432>>>(past, dWih, dWhh, dbih, dbhh, fcw, fcb, out);
}

// round 13
// speedup vs baseline: 1.3035x; 1.3035x over previous
#include <cuda_runtime.h>
#include <math.h>

// Problem constants
#define NN    65536
#define EE    1048576
#define TPAST 20
#define TFUT  40
#define HK    48
#define H3    144
#define D3    432

#define CAP1  4096
#define CAPE  16384
#define MAX2  8192

#define NB    1024    // edge-pass grid

// ---------------- device scratch ----------------
__device__ float g_deg[NN];
__device__ int   g_slot1[NN];
__device__ int   g_slot2[NN];
__device__ unsigned g_bm1[NN / 32];
__device__ unsigned g_bm12[NN / 32];
__device__ int   g_s1rows[CAP1];
__device__ float g_s1w[CAP1];
__device__ int   g_s1nodes[CAP1];
__device__ int   g_s2erow[CAPE];
__device__ int   g_s2ecol[CAPE];
__device__ float g_s2ew[CAPE];
__device__ int   g_s2nodes[MAX2];
__device__ float g_xw1[MAX2 * HK];
__device__ float g_x1[CAP1 * HK];
__device__ float g_x1acc[CAP1 * HK];
__device__ float g_interact[HK];
__device__ float g_target[HK];
__device__ float g_futv[HK];
// transposed encoder weights: WT[j*H3 + r] = W[r*HK + j]
__device__ float g_pWihT[HK * H3];
__device__ float g_pWhhT[HK * H3];
__device__ float g_fWihT[HK * H3];
__device__ float g_fWhhT[HK * H3];
__device__ int g_s1cnt = 0, g_n1 = 0, g_s2ecnt = 0, g_n2 = 0;
__device__ int g_doneA = 0;

__device__ __forceinline__ float sigmoidf(float x) { return 1.0f / (1.0f + __expf(-x)); }
__device__ __forceinline__ float sigmoidp(float x) { return 1.0f / (1.0f + expf(-x)); }

// ---------------- prepT: transpose the 4 encoder GRU weight matrices ----------------
__global__ void k_prepT(const float* __restrict__ pWih, const float* __restrict__ pWhh,
                        const float* __restrict__ fWih, const float* __restrict__ fWhh) {
    int l = blockIdx.x * 256 + threadIdx.x;
    if (l >= H3 * HK) return;
    int r = l / HK, j = l - r * HK;
    g_pWihT[j * H3 + r] = pWih[l];
    g_pWhhT[j * H3 + r] = pWhh[l];
    g_fWihT[j * H3 + r] = fWih[l];
    g_fWhhT[j * H3 + r] = fWhh[l];
}

// ---------------- passA: striped init + scan in-edges of node 0; last block builds S1 ----------------
__global__ void k_passA(const int* __restrict__ ei, const float* __restrict__ ew) {
    int tid = threadIdx.x;
    int gt = blockIdx.x * 256 + tid;
    if (gt < NN) { g_deg[gt] = 0.f; g_slot1[gt] = -1; g_slot2[gt] = -1; }
    if (gt < NN / 32) { g_bm1[gt] = 0u; g_bm12[gt] = 0u; }
    if (gt < CAP1 * HK) g_x1acc[gt] = 0.f;
    if (gt < EE / 4) {
        int4 c = reinterpret_cast<const int4*>(ei + EE)[gt];
        if (c.x == 0 || c.y == 0 || c.z == 0 || c.w == 0) {
            int cc[4] = {c.x, c.y, c.z, c.w};
            #pragma unroll
            for (int q = 0; q < 4; q++) {
                if (cc[q] == 0) {
                    int e = gt * 4 + q;
                    int pos = atomicAdd(&g_s1cnt, 1);
                    if (pos < CAP1) { g_s1rows[pos] = ei[e]; g_s1w[pos] = ew[e]; }
                }
            }
        }
    }
    __threadfence();
    __syncthreads();
    __shared__ int slast;
    if (tid == 0) slast = (atomicAdd(&g_doneA, 1) == NB - 1) ? 1 : 0;
    __syncthreads();
    if (!slast) return;
    __threadfence();
    int n = min(g_s1cnt, CAP1);
    for (int i = tid; i <= n; i += 256) {
        int v = (i == n) ? 0 : g_s1rows[i];
        if (atomicCAS(&g_slot1[v], -1, -2) == -1) {
            int s = atomicAdd(&g_n1, 1);
            if (s < CAP1) g_s1nodes[s] = v;
            g_slot1[v] = s;
            atomicOr(&g_bm1[v >> 5], 1u << (v & 31));
        }
        if (atomicCAS(&g_slot2[v], -1, -2) == -1) {
            int s = atomicAdd(&g_n2, 1);
            if (s < MAX2) g_s2nodes[s] = v;
            g_slot2[v] = s;
            g_deg[v] = 1.0f;
            atomicOr(&g_bm12[v >> 5], 1u << (v & 31));
        }
    }
    __syncthreads();
    if (tid == 0) g_doneA = 0;
}

// ---------------- passB ----------------
__global__ void k_passB(const int* __restrict__ ei, const float* __restrict__ ew) {
    int e4 = blockIdx.x * 256 + threadIdx.x;
    if (e4 >= EE / 4) return;
    int4 c = reinterpret_cast<const int4*>(ei + EE)[e4];
    int cc[4] = {c.x, c.y, c.z, c.w};
    #pragma unroll
    for (int q = 0; q < 4; q++) {
        int col = cc[q];
        if ((g_bm1[col >> 5] >> (col & 31)) & 1u) {
            int e = e4 * 4 + q;
            int row = ei[e];
            int pos = atomicAdd(&g_s2ecnt, 1);
            if (pos < CAPE) { g_s2erow[pos] = row; g_s2ecol[pos] = col; g_s2ew[pos] = ew[e]; }
            if (atomicCAS(&g_slot2[row], -1, -2) == -1) {
                int s = atomicAdd(&g_n2, 1);
                if (s < MAX2) g_s2nodes[s] = row;
                g_slot2[row] = s;
                g_deg[row] = 1.0f;
                atomicOr(&g_bm12[row >> 5], 1u << (row & 31));
            }
        }
    }
}

// ---------------- passC ----------------
__global__ void k_passC(const int* __restrict__ ei, const float* __restrict__ ew) {
    int e4 = blockIdx.x * 256 + threadIdx.x;
    if (e4 >= EE / 4) return;
    int4 c = reinterpret_cast<const int4*>(ei + EE)[e4];
    int cc[4] = {c.x, c.y, c.z, c.w};
    #pragma unroll
    for (int q = 0; q < 4; q++) {
        int col = cc[q];
        if ((g_bm12[col >> 5] >> (col & 31)) & 1u)
            atomicAdd(&g_deg[col], ew[e4 * 4 + q]);
    }
}

// ---------------- conv1d+GRU sequence (per-block, coalesced transposed weights) ----------------
__device__ void gru_seq(const float* __restrict__ xin, int T,
                        const float* __restrict__ cw, const float* __restrict__ cb,
                        const float* __restrict__ WihT, const float* __restrict__ WhhT,
                        const float* __restrict__ bih, const float* __restrict__ bhh,
                        float* xs, float* xe, float* ga, float* gb, float* h) {
    int tid = threadIdx.x;
    for (int i = tid; i < 2 * T; i += blockDim.x) xs[i] = xin[i];
    if (tid < HK) h[tid] = 0.f;
    __syncthreads();
    for (int idx = tid; idx < T * HK; idx += blockDim.x) {
        int t = idx / HK, k = idx - t * HK;
        float acc = cb[k];
        #pragma unroll
        for (int j = 0; j < 3; j++) {
            int tt = t + j - 1;
            if (tt >= 0 && tt < T)
                acc += xs[tt * 2 + 0] * cw[(k * 2 + 0) * 3 + j]
                     + xs[tt * 2 + 1] * cw[(k * 2 + 1) * 3 + j];
        }
        xe[idx] = fmaxf(acc, 0.f);
    }
    float wi[HK], wh[HK];
    float bi = 0.f, bh = 0.f;
    if (tid < H3) {
        #pragma unroll
        for (int j = 0; j < HK; j++) { wi[j] = WihT[j * H3 + tid]; wh[j] = WhhT[j * H3 + tid]; }
        bi = bih[tid]; bh = bhh[tid];
    }
    __syncthreads();
    for (int t = 0; t < T; t++) {
        if (tid < H3) {
            float a0 = bi, a1 = 0.f, b0 = bh, b1 = 0.f;
            const float* xt = &xe[t * HK];
            #pragma unroll
            for (int j = 0; j < HK; j += 2) {
                a0 += wi[j] * xt[j];     a1 += wi[j + 1] * xt[j + 1];
                b0 += wh[j] * h[j];      b1 += wh[j + 1] * h[j + 1];
            }
            ga[tid] = a0 + a1; gb[tid] = b0 + b1;
        }
        __syncthreads();
        float hn = 0.f;
        if (tid < HK) {
            float r = sigmoidp(ga[tid] + gb[tid]);
            float z = sigmoidp(ga[HK + tid] + gb[HK + tid]);
            float n = tanhf(ga[2 * HK + tid] + r * gb[2 * HK + tid]);
            hn = (1.f - z) * n + z * h[tid];
        }
        __syncthreads();
        if (tid < HK) h[tid] = hn;
        __syncthreads();
    }
}

__global__ __launch_bounds__(160) void k_gru_all(
    const float* __restrict__ x,
    const float* __restrict__ past, const float* __restrict__ future,
    const float* __restrict__ cpw, const float* __restrict__ cpb,
    const float* __restrict__ cfw, const float* __restrict__ cfb,
    const float* __restrict__ pbih, const float* __restrict__ pbhh,
    const float* __restrict__ fbih, const float* __restrict__ fbhh,
    const float* __restrict__ g1w) {
    __shared__ float xs[2 * TFUT], xe[TFUT * HK], ga[H3], gb[H3], h[HK];
    if (blockIdx.x == 0) {
        gru_seq(past, TPAST, cpw, cpb, g_pWihT, g_pWhhT, pbih, pbhh, xs, xe, ga, gb, h);
        if (threadIdx.x < HK) g_target[threadIdx.x] = h[threadIdx.x];
        return;
    }
    if (blockIdx.x == 1) {
        gru_seq(future, TFUT, cfw, cfb, g_fWihT, g_fWhhT, fbih, fbhh, xs, xe, ga, gb, h);
        if (threadIdx.x < HK) g_futv[threadIdx.x] = h[threadIdx.x];
        return;
    }
    int n2 = min(g_n2, MAX2);
    for (int i = blockIdx.x - 2; i < n2; i += gridDim.x - 2) {
        int node = g_s2nodes[i];
        gru_seq(x + (size_t)node * (2 * TPAST), TPAST, cpw, cpb, g_pWihT, g_pWhhT, pbih, pbhh,
                xs, xe, ga, gb, h);
        if (threadIdx.x < HK) {
            float acc = 0.f;
            #pragma unroll
            for (int j = 0; j < HK; j++) acc += h[j] * g1w[threadIdx.x * HK + j];
            g_xw1[i * HK + threadIdx.x] = acc;
        }
        __syncthreads();
    }
}

// ---------------- GCN cone ----------------
__global__ void k_layer1() {
    int ne = min(g_s2ecnt, CAPE);
    int total = ne * HK;
    int stride = gridDim.x * blockDim.x;
    for (int idx = blockIdx.x * blockDim.x + threadIdx.x; idx < total; idx += stride) {
        int e = idx / HK, k = idx - e * HK;
        int row = g_s2erow[e], col = g_s2ecol[e];
        float norm = rsqrtf(g_deg[row]) * g_s2ew[e] * rsqrtf(g_deg[col]);
        int s2 = g_slot2[row];
        int s1 = g_slot1[col];
        if (s2 >= 0 && s2 < MAX2 && s1 >= 0 && s1 < CAP1)
            atomicAdd(&g_x1acc[s1 * HK + k], g_xw1[s2 * HK + k] * norm);
    }
}

__global__ void k_layer2(const float* __restrict__ b1,
                         const float* __restrict__ g2w, const float* __restrict__ g2b) {
    __shared__ float coef[1024];
    __shared__ float xagg[HK];
    int tid = threadIdx.x;
    int n1 = min(g_n1, CAP1);
    for (int idx = tid; idx < n1 * HK; idx += blockDim.x) {
        int s = idx / HK, k = idx - s * HK;
        int v = g_s1nodes[s];
        float self = g_xw1[g_slot2[v] * HK + k] / g_deg[v];
        g_x1[idx] = fmaxf(g_x1acc[idx] + self + b1[k], 0.f);
    }
    int n1c = min(n1, 1024);
    int ncnt = min(g_s1cnt, CAP1);
    for (int i = tid; i < n1c; i += blockDim.x) coef[i] = 0.f;
    __syncthreads();
    float d0 = rsqrtf(g_deg[0]);
    for (int i = tid; i < ncnt; i += blockDim.x) {
        int row = g_s1rows[i];
        float nrm = rsqrtf(g_deg[row]) * g_s1w[i] * d0;
        int s = g_slot1[row];
        if (s >= 0 && s < n1c) atomicAdd(&coef[s], nrm);
    }
    __syncthreads();
    if (tid == 0) coef[g_slot1[0]] += 1.0f / g_deg[0];
    __syncthreads();
    if (tid < HK) {
        float a = 0.f;
        for (int s = 0; s < n1c; s++) a += coef[s] * g_x1[s * HK + tid];
        xagg[tid] = a;
    }
    __syncthreads();
    if (tid < HK) {
        float a = g2b[tid];
        #pragma unroll
        for (int j = 0; j < HK; j++) a += xagg[j] * g2w[tid * HK + j];
        g_interact[tid] = a;
    }
    __syncthreads();
    if (tid == 0) { g_s1cnt = 0; g_n1 = 0; g_s2ecnt = 0; g_n2 = 0; }
}

// ---------------- decoder: h-dim partitioned cluster, st.async + mbarrier (proven) ----------------
__device__ __forceinline__ unsigned smem_u32(const void* p) {
    return (unsigned)__cvta_generic_to_shared(p);
}
__device__ __forceinline__ unsigned ctarank_() {
    unsigned r; asm("mov.u32 %0, %%cluster_ctarank;" : "=r"(r)); return r;
}
__device__ __forceinline__ void mbar_init(unsigned mbar, unsigned cnt) {
    asm volatile("mbarrier.init.shared.b64 [%0], %1;" :: "r"(mbar), "r"(cnt) : "memory");
}
__device__ __forceinline__ void mbar_arrive_expect(unsigned mbar, unsigned bytes) {
    asm volatile("mbarrier.arrive.expect_tx.shared.b64 _, [%0], %1;"
                 :: "r"(mbar), "r"(bytes) : "memory");
}
__device__ __forceinline__ void mbar_wait(unsigned mbar, unsigned phase) {
    asm volatile(
        "{\n\t.reg .pred P;\n\t"
        "WL_%=:\n\t"
        "mbarrier.try_wait.parity.shared.b64 P, [%0], %1;\n\t"
        "@!P bra WL_%=;\n\t}"
        :: "r"(mbar), "r"(phase) : "memory");
}
__device__ __forceinline__ void st_async_f32(unsigned raddr, float v, unsigned rmbar) {
    asm volatile("st.async.shared::cluster.mbarrier::complete_tx::bytes.f32 [%0], %1, [%2];"
                 :: "r"(raddr), "f"(v), "r"(rmbar) : "memory");
}
__device__ __forceinline__ unsigned mapa_(unsigned laddr, unsigned rank) {
    unsigned r;
    asm volatile("mapa.shared::cluster.u32 %0, %1, %2;" : "=r"(r) : "r"(laddr), "r"(rank));
    return r;
}

__global__ __launch_bounds__(432, 1) __cluster_dims__(3, 1, 1)
void k_decoder(const float* __restrict__ past,
               const float* __restrict__ dWih, const float* __restrict__ dWhh,
               const float* __restrict__ dbih, const float* __restrict__ dbhh,
               const float* __restrict__ fcw, const float* __restrict__ fcb,
               float* __restrict__ out) {
    __shared__ __align__(16) float hbuf[2][H3];
    __shared__ float part[432];
    __shared__ float gbl[H3];
    __shared__ float ga0[H3];
    __shared__ float sbihL[H3], sbhhL[H3];
    __shared__ float sc[H3];
    __shared__ float sfcw[2 * H3];
    __shared__ float pres[2];
    __shared__ __align__(8) unsigned long long mbs[2];

    int tid = threadIdx.x;
    unsigned ct = ctarank_();
    int rl = tid % H3, p = tid / H3;
    int grow = (rl / 48) * H3 + (int)ct * 48 + (rl % 48);

    unsigned mb0 = smem_u32(&mbs[0]), mb1 = smem_u32(&mbs[1]);
    if (tid == 0) { mbar_init(mb0, 1); mbar_init(mb1, 1); }

    float w[48];
    {
        const float4* wp = reinterpret_cast<const float4*>(dWhh + grow * H3 + p * 48);
        #pragma unroll
        for (int j = 0; j < 12; j++) {
            float4 v = wp[j];
            w[4 * j + 0] = v.x; w[4 * j + 1] = v.y; w[4 * j + 2] = v.z; w[4 * j + 3] = v.w;
        }
    }
    if (tid < HK) { sc[tid] = g_interact[tid]; sc[HK + tid] = g_target[tid]; sc[2 * HK + tid] = g_futv[tid]; }
    if (tid < H3) { hbuf[0][tid] = 0.f; sbihL[tid] = dbih[grow]; sbhhL[tid] = dbhh[grow]; }
    if (ct == 0) {
        if (tid >= H3 && tid < H3 + 2 * H3) sfcw[tid - H3] = fcw[tid - H3];
        if (tid < 2) pres[tid] = past[(TPAST - 1) * 2 + tid];
    }
    __syncthreads();

    {
        float a = 0.f;
        const float* wi = dWih + grow * H3 + p * 48;
        #pragma unroll
        for (int j = 0; j < 48; j++) a += wi[j] * sc[p * 48 + j];
        part[tid] = a;
    }
    __syncthreads();
    if (tid < H3) ga0[tid] = part[tid] + part[tid + H3] + part[tid + 2 * H3] + sbihL[tid];
    __syncthreads();
    asm volatile("barrier.cluster.arrive.aligned;" ::: "memory");
    asm volatile("barrier.cluster.wait.aligned;" ::: "memory");

    int base = (int)ct * 48;
    for (int i = 0; i < TFUT; i++) {
        int cur = i & 1, bi = cur ^ 1;
        unsigned mbar = bi ? mb1 : mb0;
        unsigned ph = (i >> 1) & 1;
        {
            const float4* hp4 = reinterpret_cast<const float4*>(&hbuf[cur][p * 48]);
            float a0 = 0.f, a1 = 0.f, a2 = 0.f, a3 = 0.f;
            #pragma unroll
            for (int j = 0; j < 12; j++) {
                float4 hv = hp4[j];
                a0 += w[4 * j + 0] * hv.x;
                a1 += w[4 * j + 1] * hv.y;
                a2 += w[4 * j + 2] * hv.z;
                a3 += w[4 * j + 3] * hv.w;
            }
            part[tid] = (a0 + a1) + (a2 + a3);
        }
        __syncthreads();
        if (tid < H3) gbl[tid] = part[tid] + part[tid + H3] + part[tid + 2 * H3] + sbhhL[tid];
        __syncthreads();
        if (tid < 48) {
            float gar = i ? sbihL[tid]      : ga0[tid];
            float gaz = i ? sbihL[48 + tid] : ga0[48 + tid];
            float gan = i ? sbihL[96 + tid] : ga0[96 + tid];
            float r = sigmoidf(gar + gbl[tid]);
            float z = sigmoidf(gaz + gbl[48 + tid]);
            float n = tanhf(gan + r * gbl[96 + tid]);
            float hn = (1.f - z) * n + z * hbuf[cur][base + tid];
            hbuf[bi][base + tid] = hn;
            unsigned la = smem_u32(&hbuf[bi][base + tid]);
            st_async_f32(mapa_(la, (ct + 1) % 3), hn, mapa_(mbar, (ct + 1) % 3));
            st_async_f32(mapa_(la, (ct + 2) % 3), hn, mapa_(mbar, (ct + 2) % 3));
        }
        if (tid == 64) mbar_arrive_expect(mbar, 384);
        __syncthreads();
        mbar_wait(mbar, ph);
        if (ct == 0 && tid >= 64 && tid < 128) {
            int d = (tid - 64) >> 5, lane = tid & 31;
            float a = 0.f;
            #pragma unroll
            for (int j = lane; j < H3; j += 32) a += hbuf[bi][j] * sfcw[d * H3 + j];
            #pragma unroll
            for (int off = 16; off; off >>= 1) a += __shfl_down_sync(0xffffffffu, a, off);
            if (lane == 0) { pres[d] += a + fcb[d]; out[i * 2 + d] = pres[d]; }
        }
        __syncthreads();
    }
}

// ---------------- launch ----------------
extern "C" void kernel_launch(void* const* d_in, const int* in_sizes, int n_in,
                              void* d_out, int out_size) {
    (void)in_sizes; (void)n_in; (void)out_size;
    const float* past   = (const float*)d_in[0];
    const float* future = (const float*)d_in[1];
    const float* x      = (const float*)d_in[2];
    const int*   ei     = (const int*)  d_in[3];
    const float* ew     = (const float*)d_in[4];
    const float* cpw  = (const float*)d_in[5];
    const float* cpb  = (const float*)d_in[6];
    const float* cfw  = (const float*)d_in[7];
    const float* cfb  = (const float*)d_in[8];
    const float* pWih = (const float*)d_in[9];
    const float* pWhh = (const float*)d_in[10];
    const float* pbih = (const float*)d_in[11];
    const float* pbhh = (const float*)d_in[12];
    const float* fWih = (const float*)d_in[13];
    const float* fWhh = (const float*)d_in[14];
    const float* fbih = (const float*)d_in[15];
    const float* fbhh = (const float*)d_in[16];
    const float* dWih = (const float*)d_in[17];
    const float* dWhh = (const float*)d_in[18];
    const float* dbih = (const float*)d_in[19];
    const float* dbhh = (const float*)d_in[20];
    const float* fcw  = (const float*)d_in[21];
    const float* fcb  = (const float*)d_in[22];
    const float* g1w  = (const float*)d_in[23];
    const float* g1b  = (const float*)d_in[24];
    const float* g2w  = (const float*)d_in[25];
    const float* g2b  = (const float*)d_in[26];
    float* out = (float*)d_out;

    k_prepT<<<27, 256>>>(pWih, pWhh, fWih, fWhh);
    k_passA<<<NB, 256>>>(ei, ew);
    k_passB<<<NB, 256>>>(ei, ew);
    k_passC<<<NB, 256>>>(ei, ew);
    k_gru_all<<<1026, 160>>>(x, past, future, cpw, cpb, cfw, cfb,
                             pbih, pbhh, fbih, fbhh, g1w);
    k_layer1<<<64, 256>>>();
    k_layer2<<<1, 256>>>(g1b, g2w, g2b);
    k_decoder<<<3, 432>>>(past, dWih, dWhh, dbih, dbhh, fcw, fcb, out);
}